// round 17
// baseline (speedup 1.0000x reference)
#include <cuda_runtime.h>

// GradientAwareAreaUtil: per-image  sum(Y) - 0.1*(sum|vdiff| + sum|hdiff|)
// B=512, 256x256 fp32. Synthesis of R10 (tail-friendly small CTAs) and
// R11/R14 (minimal-traffic boundary exchange):
//   grid = 4096 CTAs (eighth image = 32 rows), 128 threads = 4 warps,
//   warp = 8-row band, lane owns cols [8l, 8l+8) as two float4 (LDG.128).
//   Warps load ONLY their own rows; band-boundary vdiffs use the next warp's
//   first row parked in smem; only the CTA's last boundary row is re-read
//   from global (clamped at image end) -> +3.1% traffic. Warp 3's boundary
//   load is hoisted to the top so its DRAM latency overlaps the main loop.

#define H 256
#define W 256
#define R4 (W / 4)
#define BATCH 512
#define PENALTY 0.1f

__device__ __forceinline__ float vdiff8(const float4& a0, const float4& a1,
                                        const float4& b0, const float4& b1) {
    return fabsf(a0.x - b0.x) + fabsf(a0.y - b0.y) + fabsf(a0.z - b0.z) + fabsf(a0.w - b0.w)
         + fabsf(a1.x - b1.x) + fabsf(a1.y - b1.y) + fabsf(a1.z - b1.z) + fabsf(a1.w - b1.w);
}

__global__ void __launch_bounds__(128, 16)
grad_area_kernel(const float* __restrict__ Y, float* __restrict__ out)
{
    __shared__ float s_first[4][W];       // each warp's first band row (4 KB)
    __shared__ float s_area[4];
    __shared__ float s_grad[4];

    const int cta  = blockIdx.x;          // 0..4095
    const int b    = cta >> 3;            // image
    const int oct  = cta & 7;             // eighth (32 rows)
    const int warp = threadIdx.x >> 5;
    const int lane = threadIdx.x & 31;
    const int col  = lane * 8;

    const int r0 = oct * 32 + warp * 8;   // this warp's band start

    const float4* base = (const float4*)(Y + (size_t)b * (H * W)) + 2 * lane;

    // warp 3: cross-CTA boundary row, issued FIRST so its latency overlaps
    // the entire main loop (clamped: image's last row pairs with itself -> 0)
    float4 N0, N1;
    if (warp == 3) {
        const float4* p = base + (size_t)min(r0 + 8, H - 1) * R4;
        N0 = p[0];
        N1 = p[1];
    }

    // ring[r%3] holds row r's 8 floats for this lane
    float4 ring[3][2];
    #pragma unroll
    for (int i = 0; i < 3; ++i) {
        const float4* p = base + (size_t)(r0 + i) * R4;
        ring[i][0] = p[0];
        ring[i][1] = p[1];
    }

    // park first band row for warp-1's boundary diff
    *(float4*)&s_first[warp][col]     = ring[0][0];
    *(float4*)&s_first[warp][col + 4] = ring[0][1];

    float area = 0.0f, grad = 0.0f;

    #pragma unroll
    for (int i = 0; i < 8; ++i) {
        const int s  = i % 3;
        const int s1 = (i + 1) % 3;

        float4 A0 = ring[s][0], A1 = ring[s][1];          // row r0+i

        if (i + 3 <= 7) {                                  // refill rows r0+3..r0+7
            const float4* p = base + (size_t)(r0 + i + 3) * R4;
            ring[s][0] = p[0];
            ring[s][1] = p[1];
        }

        // area
        area += ((A0.x + A0.y) + (A0.z + A0.w)) + ((A1.x + A1.y) + (A1.z + A1.w));

        // horizontal: 7 in-lane diffs + 1 cross-lane
        grad += fabsf(A0.x - A0.y) + fabsf(A0.y - A0.z) + fabsf(A0.z - A0.w)
              + fabsf(A0.w - A1.x)
              + fabsf(A1.x - A1.y) + fabsf(A1.y - A1.z) + fabsf(A1.z - A1.w);
        float nf = __shfl_down_sync(0xffffffffu, A0.x, 1);
        if (lane < 31)
            grad += fabsf(A1.w - nf);

        // vertical: internal pairs (rows r0+i -> r0+i+1, i<7)
        if (i < 7) {
            float4 B0 = ring[s1][0], B1 = ring[s1][1];
            grad += vdiff8(A0, A1, B0, B1);
        }
    }
    // ring[1] == band's last row (r0+7)

    __syncthreads();

    if (warp < 3) {
        N0 = *(const float4*)&s_first[warp + 1][col];
        N1 = *(const float4*)&s_first[warp + 1][col + 4];
    }
    // boundary vdiff: band's last row vs next band's first row
    grad += vdiff8(ring[1][0], ring[1][1], N0, N1);

    // warp reduction
    #pragma unroll
    for (int off = 16; off > 0; off >>= 1) {
        area += __shfl_xor_sync(0xffffffffu, area, off);
        grad += __shfl_xor_sync(0xffffffffu, grad, off);
    }
    if (lane == 0) { s_area[warp] = area; s_grad[warp] = grad; }
    __syncthreads();

    if (threadIdx.x == 0) {
        float ta = (s_area[0] + s_area[1]) + (s_area[2] + s_area[3]);
        float tg = (s_grad[0] + s_grad[1]) + (s_grad[2] + s_grad[3]);
        atomicAdd(out + b, ta - PENALTY * tg);
    }
}

extern "C" void kernel_launch(void* const* d_in, const int* in_sizes, int n_in,
                              void* d_out, int out_size)
{
    const float* Y   = (const float*)d_in[0];
    float*       out = (float*)d_out;
    cudaMemsetAsync(out, 0, BATCH * sizeof(float), 0);
    grad_area_kernel<<<BATCH * 8, 128>>>(Y, out);
}